// round 15
// baseline (speedup 1.0000x reference)
#include <cuda_runtime.h>
#include <cuda_fp16.h>
#include <math.h>
#include <stdint.h>

#define BATCH 2
#define SEQ   2048
#define DIMM  4096
#define NH    32
#define NKV   8
#define HD    128
#define MROWS (BATCH * SEQ)          // 4096
#define KVD   (NKV * HD)             // 512
#define NQKV  (DIMM + 2 * KVD)       // 5120

// ---------------- fp16 scratch (static device globals) -----------------------
__device__ __half g_xh[(size_t)MROWS * DIMM];
__device__ __half g_wh[(size_t)NQKV * DIMM];
__device__ __half g_woh[(size_t)DIMM * DIMM];
__device__ __half g_qh[(size_t)MROWS * DIMM];
__device__ __half g_kh[(size_t)MROWS * KVD];
__device__ __half g_vh[(size_t)MROWS * KVD];
__device__ __half g_ah[(size_t)MROWS * DIMM];

__device__ __forceinline__ uint32_t f2h2(float a, float b) {
    __half2 h = __float22half2_rn(make_float2(a, b));
    return *reinterpret_cast<uint32_t*>(&h);
}
__device__ __forceinline__ float ex2(float x) {
    float r;
    asm("ex2.approx.f32 %0, %1;" : "=f"(r) : "f"(x));
    return r;
}
__device__ __forceinline__ void mma16816(float* d, const uint32_t* a,
                                         uint32_t b0, uint32_t b1) {
    asm volatile(
        "mma.sync.aligned.m16n8k16.row.col.f32.f16.f16.f32 "
        "{%0,%1,%2,%3},{%4,%5,%6,%7},{%8,%9},{%0,%1,%2,%3};"
        : "+f"(d[0]), "+f"(d[1]), "+f"(d[2]), "+f"(d[3])
        : "r"(a[0]), "r"(a[1]), "r"(a[2]), "r"(a[3]), "r"(b0), "r"(b1));
}
__device__ __forceinline__ void ldsm4(uint32_t* r, uint32_t addr) {
    asm volatile("ldmatrix.sync.aligned.m8n8.x4.shared.b16 {%0,%1,%2,%3}, [%4];"
                 : "=r"(r[0]), "=r"(r[1]), "=r"(r[2]), "=r"(r[3]) : "r"(addr));
}
__device__ __forceinline__ void ldsm4t(uint32_t* r, uint32_t addr) {
    asm volatile("ldmatrix.sync.aligned.m8n8.x4.trans.shared.b16 {%0,%1,%2,%3}, [%4];"
                 : "=r"(r[0]), "=r"(r[1]), "=r"(r[2]), "=r"(r[3]) : "r"(addr));
}
__device__ __forceinline__ void cpa16(uint32_t dst, const void* src) {
    asm volatile("cp.async.cg.shared.global [%0], [%1], 16;" :: "r"(dst), "l"(src));
}
#define CP_COMMIT() asm volatile("cp.async.commit_group;")

// log2e / sqrt(hd) folded into Q at projection epilogue
#define QSCL (0.08838834764831845f * 1.44269504088896340736f)
#define ONES2 0x3C003C00u   // half2(1.0, 1.0)

// ---------------- fp32 -> fp16 convert (64B per thread) ----------------------
__global__ void f2h_kernel(const float* __restrict__ in, __half* __restrict__ out,
                           int n16) {
    int i = blockIdx.x * blockDim.x + threadIdx.x;
    if (i >= n16) return;
    const float4* p = reinterpret_cast<const float4*>(in) + 4 * (size_t)i;
    float4 a = p[0], b = p[1], c = p[2], d = p[3];
    uint4* q = reinterpret_cast<uint4*>(out) + 2 * (size_t)i;
    q[0] = make_uint4(f2h2(a.x, a.y), f2h2(a.z, a.w), f2h2(b.x, b.y), f2h2(b.z, b.w));
    q[1] = make_uint4(f2h2(c.x, c.y), f2h2(c.z, c.w), f2h2(d.x, d.y), f2h2(d.z, d.w));
}

// ============================================================================
// fp16 GEMM, 3-stage cp.async pipeline (R9-proven config):
// CTA 128x128x64(halves), 8 warps (2x4), warp tile 64x32.
// smem rows: 64 halves = 8 x 16B chunks, phys chunk = ch ^ (row & 7).
// mode 0: fp32 out; mode 1: segmented fp16 q/k/v out, fused RoPE (+QSCL on q).
// ============================================================================
#define GBM 128
#define GBN 128
#define GBK 64
#define G_STAGE_BYTES ((GBM + GBN) * GBK * 2)     // 32768
#define G_SMEM (3 * G_STAGE_BYTES)                // 98304

__global__ __launch_bounds__(256, 2) void h16_gemm(
    const __half* __restrict__ A, const __half* __restrict__ B, int K,
    float* __restrict__ Cf,
    __half* __restrict__ qo, __half* __restrict__ ko, __half* __restrict__ vo,
    const float* __restrict__ fc, const float* __restrict__ fs, int mode) {
    extern __shared__ __half smh[];
    const uint32_t smb = (uint32_t)__cvta_generic_to_shared(smh);

    const int tid = threadIdx.x, lane = tid & 31, wid = tid >> 5;
    const int bm = blockIdx.y * GBM, bn = blockIdx.x * GBN;
    const int wm = (wid & 1) * 64, wn = (wid >> 1) * 32;

    const int srow = tid >> 1;
    const int scb  = (tid & 1) * 4;
    const __half* Agp = A + (size_t)(bm + srow) * K + scb * 8;
    const __half* Bgp = B + (size_t)(bn + srow) * K + scb * 8;
    uint32_t adst[4], bdst[4];
#pragma unroll
    for (int c = 0; c < 4; c++) {
        const int sw = (scb + c) ^ (srow & 7);
        adst[c] = (uint32_t)((srow * 8 + sw) * 16);
        bdst[c] = adst[c] + (uint32_t)(GBM * GBK * 2);
    }

    float acc[4][4][4];
#pragma unroll
    for (int i = 0; i < 4; i++)
#pragma unroll
        for (int j = 0; j < 4; j++)
#pragma unroll
            for (int c = 0; c < 4; c++) acc[i][j][c] = 0.f;

    const int T = K / GBK;
#pragma unroll
    for (int s = 0; s < 2; s++) {
        const uint32_t sb = smb + s * G_STAGE_BYTES;
#pragma unroll
        for (int c = 0; c < 4; c++) {
            cpa16(sb + adst[c], Agp + (size_t)s * GBK + c * 8);
            cpa16(sb + bdst[c], Bgp + (size_t)s * GBK + c * 8);
        }
        CP_COMMIT();
    }
    asm volatile("cp.async.wait_group 1;");
    __syncthreads();

    const int grp = lane >> 3, ls = lane & 7, qa = lane >> 2;

    int rs = 0;
    for (int t = 0; t < T; t++) {
        const int wt = t + 2;
        if (wt < T) {
            const int wsx = (rs + 2) % 3;
            const uint32_t sb = smb + wsx * G_STAGE_BYTES;
#pragma unroll
            for (int c = 0; c < 4; c++) {
                cpa16(sb + adst[c], Agp + (size_t)wt * GBK + c * 8);
                cpa16(sb + bdst[c], Bgp + (size_t)wt * GBK + c * 8);
            }
        }
        CP_COMMIT();

        const uint32_t Ab = smb + rs * G_STAGE_BYTES;
        const uint32_t Bb = Ab + (uint32_t)(GBM * GBK * 2);
#pragma unroll
        for (int kk = 0; kk < 4; kk++) {
            uint32_t af[4][4], bf[2][4];
#pragma unroll
            for (int mt = 0; mt < 4; mt++) {
                const int row = wm + mt * 16 + ls + ((grp & 1) << 3);
                const int ch  = 2 * kk + (grp >> 1);
                ldsm4(af[mt], Ab + ((row * 8 + (ch ^ (row & 7))) << 4));
            }
#pragma unroll
            for (int g = 0; g < 2; g++) {
                const int row = wn + g * 16 + ls + ((grp >> 1) << 3);
                const int ch  = 2 * kk + (grp & 1);
                ldsm4(bf[g], Bb + ((row * 8 + (ch ^ (row & 7))) << 4));
            }
#pragma unroll
            for (int mt = 0; mt < 4; mt++)
#pragma unroll
                for (int g = 0; g < 2; g++) {
                    mma16816(acc[mt][2 * g],     af[mt], bf[g][0], bf[g][1]);
                    mma16816(acc[mt][2 * g + 1], af[mt], bf[g][2], bf[g][3]);
                }
        }

        asm volatile("cp.async.wait_group 1;");
        __syncthreads();
        rs = (rs + 1) % 3;
    }

    // ---------------- epilogue ----------------
    if (mode == 0) {
#pragma unroll
        for (int mt = 0; mt < 4; mt++)
#pragma unroll
            for (int nt = 0; nt < 4; nt++) {
                const int row = bm + wm + mt * 16 + qa;
                const int col = bn + wn + nt * 8 + (lane & 3) * 2;
                *reinterpret_cast<float2*>(&Cf[(size_t)row * DIMM + col]) =
                    make_float2(acc[mt][nt][0], acc[mt][nt][1]);
                *reinterpret_cast<float2*>(&Cf[(size_t)(row + 8) * DIMM + col]) =
                    make_float2(acc[mt][nt][2], acc[mt][nt][3]);
            }
    } else {
        __half* outp; int colbase, stride; bool rope; float oscl;
        if (bn < DIMM)            { outp = qo; colbase = bn;              stride = DIMM; rope = true;  oscl = QSCL; }
        else if (bn < DIMM + KVD) { outp = ko; colbase = bn - DIMM;       stride = KVD;  rope = true;  oscl = 1.f; }
        else                      { outp = vo; colbase = bn - DIMM - KVD; stride = KVD;  rope = false; oscl = 1.f; }
#pragma unroll
        for (int mt = 0; mt < 4; mt++)
#pragma unroll
            for (int nt = 0; nt < 4; nt++) {
                const int row0 = bm + wm + mt * 16 + qa;
                const int row1 = row0 + 8;
                const int col  = colbase + wn + nt * 8 + (lane & 3) * 2;
                float2 v0 = make_float2(acc[mt][nt][0], acc[mt][nt][1]);
                float2 v1 = make_float2(acc[mt][nt][2], acc[mt][nt][3]);
                if (rope) {
                    const int i = (col & (HD - 1)) >> 1;
                    const float c0 = fc[(row0 & (SEQ - 1)) * (HD / 2) + i] * oscl;
                    const float s0 = fs[(row0 & (SEQ - 1)) * (HD / 2) + i] * oscl;
                    v0 = make_float2(v0.x * c0 - v0.y * s0, v0.x * s0 + v0.y * c0);
                    const float c1 = fc[(row1 & (SEQ - 1)) * (HD / 2) + i] * oscl;
                    const float s1 = fs[(row1 & (SEQ - 1)) * (HD / 2) + i] * oscl;
                    v1 = make_float2(v1.x * c1 - v1.y * s1, v1.x * s1 + v1.y * c1);
                }
                *reinterpret_cast<uint32_t*>(&outp[(size_t)row0 * stride + col]) = f2h2(v0.x, v0.y);
                *reinterpret_cast<uint32_t*>(&outp[(size_t)row1 * stride + col]) = f2h2(v1.x, v1.y);
            }
    }
}

// ============================================================================
// fp16 flash attention (GQA 4:1), cp.async double-buffered K/V
// Q pre-scaled by 1/sqrt(hd)*log2e; MUFU ex2.approx softmax.
// Interleaved per-16-col chunk: ex2/pack -> lsum mma -> P.V mmas.
// P a-fragment order (R13-proven): {lo(n0), hi(n0), lo(n1), hi(n1)}.
// ============================================================================
#define FBR 128
#define FBC 64
#define FQB 0u
#define FKB 32768u
#define FVB 65536u
#define FKVSZ 16384u
#define F_SMEM 98304

__global__ __launch_bounds__(256, 2) void flash_h_kernel(const __half* __restrict__ q,
                                                         const __half* __restrict__ k,
                                                         const __half* __restrict__ v,
                                                         __half* __restrict__ o) {
    extern __shared__ __half smh[];
    const uint32_t smb = (uint32_t)__cvta_generic_to_shared(smh);

    const int tid  = threadIdx.x;
    const int lane = tid & 31;
    const int wid  = tid >> 5;
    const int wm   = wid * 16;

    const int qt = gridDim.x - 1 - blockIdx.x;
    const int h  = blockIdx.y;
    const int b  = blockIdx.z;
    const int kvh = h >> 2;
    const int qbase = qt * FBR;

    {
        const int row = tid >> 1, cbq = (tid & 1) * 8;
        const __half* src = &q[(((size_t)b * SEQ + qbase + row) * NH + h) * HD + cbq * 8];
#pragma unroll
        for (int c = 0; c < 8; c++) {
            const int ch = cbq + c;
            cpa16(smb + FQB + ((row * 16 + (ch ^ (row & 7))) << 4), src + c * 8);
        }
    }
    const int kvrow = tid >> 2, kvcb = (tid & 3) * 4;
    uint32_t kvdst[4];
#pragma unroll
    for (int c = 0; c < 4; c++)
        kvdst[c] = (uint32_t)((kvrow * 16 + ((kvcb + c) ^ (kvrow & 7))) << 4);

    const int nkt = 2 * qt + 2;
    {
        const size_t base = (((size_t)b * SEQ + kvrow) * NKV + kvh) * HD + kvcb * 8;
#pragma unroll
        for (int c = 0; c < 4; c++) {
            cpa16(smb + FKB + kvdst[c], &k[base + c * 8]);
            cpa16(smb + FVB + kvdst[c], &v[base + c * 8]);
        }
    }
    CP_COMMIT();
    asm volatile("cp.async.wait_group 0;");
    __syncthreads();

    float oacc[16][4];
#pragma unroll
    for (int n = 0; n < 16; n++)
#pragma unroll
        for (int c = 0; c < 4; c++) oacc[n][c] = 0.f;

    float m0 = -INFINITY, m1 = -INFINITY, l0 = 0.f, l1 = 0.f;

    const int grp = lane >> 3, ls = lane & 7;

    for (int kt = 0; kt < nkt; kt++) {
        const int kvbase = kt * FBC;
        if (kt + 1 < nkt) {
            const uint32_t ob = ((kt + 1) & 1) * FKVSZ;
            const size_t base =
                (((size_t)b * SEQ + (kt + 1) * FBC + kvrow) * NKV + kvh) * HD + kvcb * 8;
#pragma unroll
            for (int c = 0; c < 4; c++) {
                cpa16(smb + FKB + ob + kvdst[c], &k[base + c * 8]);
                cpa16(smb + FVB + ob + kvdst[c], &v[base + c * 8]);
            }
        }
        CP_COMMIT();

        const uint32_t ksb = smb + FKB + (kt & 1) * FKVSZ;
        const uint32_t vsb = smb + FVB + (kt & 1) * FKVSZ;
        const uint32_t qsb = smb + FQB;

        float sacc[8][4];
#pragma unroll
        for (int n = 0; n < 8; n++)
#pragma unroll
            for (int c = 0; c < 4; c++) sacc[n][c] = 0.f;

#pragma unroll
        for (int i = 0; i < HD / 16; i++) {
            uint32_t qf[4], kf[4];
            const int qrow = wm + ls + ((grp & 1) << 3);
            const int qch  = 2 * i + (grp >> 1);
            ldsm4(qf, qsb + (((qrow << 4) + (qch ^ (qrow & 7))) << 4));
#pragma unroll
            for (int n0 = 0; n0 < 4; n0++) {
                const int krow = n0 * 16 + ls + ((grp >> 1) << 3);
                const int kch  = 2 * i + (grp & 1);
                ldsm4(kf, ksb + (((krow << 4) + (kch ^ (krow & 7))) << 4));
                mma16816(sacc[2 * n0],     qf, kf[0], kf[1]);
                mma16816(sacc[2 * n0 + 1], qf, kf[2], kf[3]);
            }
        }

        // causal mask (scores already log2-scaled via Q)
        const int gr0 = qbase + wm + (lane >> 2);
        const int gr1 = gr0 + 8;
        const bool need_mask = (kvbase + FBC - 1) > (qbase + wm);
        if (need_mask) {
#pragma unroll
            for (int n = 0; n < 8; n++) {
                const int gc = kvbase + n * 8 + (lane & 3) * 2;
                if (gc     > gr0) sacc[n][0] = -INFINITY;
                if (gc + 1 > gr0) sacc[n][1] = -INFINITY;
                if (gc     > gr1) sacc[n][2] = -INFINITY;
                if (gc + 1 > gr1) sacc[n][3] = -INFINITY;
            }
        }

        float mx0 = -INFINITY, mx1 = -INFINITY;
#pragma unroll
        for (int n = 0; n < 8; n++) {
            mx0 = fmaxf(mx0, fmaxf(sacc[n][0], sacc[n][1]));
            mx1 = fmaxf(mx1, fmaxf(sacc[n][2], sacc[n][3]));
        }
        mx0 = fmaxf(mx0, __shfl_xor_sync(0xffffffffu, mx0, 1));
        mx0 = fmaxf(mx0, __shfl_xor_sync(0xffffffffu, mx0, 2));
        mx1 = fmaxf(mx1, __shfl_xor_sync(0xffffffffu, mx1, 1));
        mx1 = fmaxf(mx1, __shfl_xor_sync(0xffffffffu, mx1, 2));

        const float mn0 = fmaxf(m0, mx0);
        const float mn1 = fmaxf(m1, mx1);
        const float al0 = ex2(m0 - mn0);
        const float al1 = ex2(m1 - mn1);
        m0 = mn0; m1 = mn1;

        // rescale O (independent of softmax chain below; scheduler overlaps)
#pragma unroll
        for (int n = 0; n < 16; n++) {
            oacc[n][0] *= al0; oacc[n][1] *= al0;
            oacc[n][2] *= al1; oacc[n][3] *= al1;
        }

        // interleaved: per 16-col chunk, ex2/pack -> lsum mma -> P.V mmas
        float lsum[4] = {0.f, 0.f, 0.f, 0.f};
#pragma unroll
        for (int j = 0; j < FBC / 16; j++) {
            uint32_t pa[4];
#pragma unroll
            for (int s = 0; s < 2; s++) {
                const int n = 2 * j + s;
                const float p0 = ex2(sacc[n][0] - m0);
                const float p1 = ex2(sacc[n][1] - m0);
                const float p2 = ex2(sacc[n][2] - m1);
                const float p3 = ex2(sacc[n][3] - m1);
                pa[2 * s]     = f2h2(p0, p1);   // rows 0-7 slot (R13 order)
                pa[2 * s + 1] = f2h2(p2, p3);   // rows 8-15 slot
            }
            mma16816(lsum, pa, ONES2, ONES2);
#pragma unroll
            for (int n0 = 0; n0 < HD / 16; n0++) {
                uint32_t vf[4];
                const int vrow = j * 16 + ls + ((grp & 1) << 3);
                const int vch  = 2 * n0 + (grp >> 1);
                ldsm4t(vf, vsb + (((vrow << 4) + (vch ^ (vrow & 7))) << 4));
                mma16816(oacc[2 * n0],     pa, vf[0], vf[1]);
                mma16816(oacc[2 * n0 + 1], pa, vf[2], vf[3]);
            }
        }
        l0 = l0 * al0 + lsum[0];
        l1 = l1 * al1 + lsum[2];

        asm volatile("cp.async.wait_group 0;");
        __syncthreads();
    }

    const float inv0 = 1.f / l0;
    const float inv1 = 1.f / l1;
    const int gr0 = qbase + wm + (lane >> 2);
    const int gr1 = gr0 + 8;
#pragma unroll
    for (int n = 0; n < 16; n++) {
        const int col = n * 8 + (lane & 3) * 2;
        *reinterpret_cast<uint32_t*>(
            &o[((size_t)b * SEQ + gr0) * DIMM + h * HD + col]) =
            f2h2(oacc[n][0] * inv0, oacc[n][1] * inv0);
        *reinterpret_cast<uint32_t*>(
            &o[((size_t)b * SEQ + gr1) * DIMM + h * HD + col]) =
            f2h2(oacc[n][2] * inv1, oacc[n][3] * inv1);
    }
}

// ---------------- launch ------------------------------------------------------
extern "C" void kernel_launch(void* const* d_in, const int* in_sizes, int n_in,
                              void* d_out, int out_size) {
    const float* x  = (const float*)d_in[0];
    const float* wq = (const float*)d_in[1];
    const float* wk = (const float*)d_in[2];
    const float* wv = (const float*)d_in[3];
    const float* wo = (const float*)d_in[4];
    const float* fc = (const float*)d_in[5];
    const float* fs = (const float*)d_in[6];
    float* out = (float*)d_out;

    __half *xh, *wh, *woh, *qh, *kh, *vh, *ah;
    cudaGetSymbolAddress((void**)&xh,  g_xh);
    cudaGetSymbolAddress((void**)&wh,  g_wh);
    cudaGetSymbolAddress((void**)&woh, g_woh);
    cudaGetSymbolAddress((void**)&qh,  g_qh);
    cudaGetSymbolAddress((void**)&kh,  g_kh);
    cudaGetSymbolAddress((void**)&vh,  g_vh);
    cudaGetSymbolAddress((void**)&ah,  g_ah);

    cudaFuncSetAttribute(h16_gemm, cudaFuncAttributeMaxDynamicSharedMemorySize, G_SMEM);
    cudaFuncSetAttribute(flash_h_kernel, cudaFuncAttributeMaxDynamicSharedMemorySize, F_SMEM);

    // fp32 -> fp16 converts (five separate launches — proven)
    {
        const int nx = MROWS * DIMM / 16;
        f2h_kernel<<<nx / 256, 256>>>(x, xh, nx);
        const int nq = DIMM * DIMM / 16;
        f2h_kernel<<<nq / 256, 256>>>(wq, wh, nq);
        const int nk = KVD * DIMM / 16;
        f2h_kernel<<<nk / 256, 256>>>(wk, wh + (size_t)DIMM * DIMM, nk);
        f2h_kernel<<<nk / 256, 256>>>(wv, wh + (size_t)(DIMM + KVD) * DIMM, nk);
        f2h_kernel<<<nq / 256, 256>>>(wo, woh, nq);
    }

    // fused QKV projection + RoPE (+QSCL on q)
    h16_gemm<<<dim3(NQKV / GBN, MROWS / GBM), 256, G_SMEM>>>(
        xh, wh, DIMM, nullptr, qh, kh, vh, fc, fs, 1);

    // causal flash attention
    flash_h_kernel<<<dim3(SEQ / FBR, NH, BATCH), 256, F_SMEM>>>(qh, kh, vh, ah);

    // output projection (fp32 out)
    h16_gemm<<<dim3(DIMM / GBN, MROWS / GBM), 256, G_SMEM>>>(
        ah, woh, DIMM, out, nullptr, nullptr, nullptr, nullptr, nullptr, 0);
}

// round 16
// speedup vs baseline: 1.0035x; 1.0035x over previous
#include <cuda_runtime.h>
#include <cuda_fp16.h>
#include <math.h>
#include <stdint.h>

#define BATCH 2
#define SEQ   2048
#define DIMM  4096
#define NH    32
#define NKV   8
#define HD    128
#define MROWS (BATCH * SEQ)          // 4096
#define KVD   (NKV * HD)             // 512
#define NQKV  (DIMM + 2 * KVD)       // 5120

// ---------------- fp16 scratch (static device globals) -----------------------
__device__ __half g_xh[(size_t)MROWS * DIMM];
__device__ __half g_wh[(size_t)NQKV * DIMM];
__device__ __half g_woh[(size_t)DIMM * DIMM];
__device__ __half g_qh[(size_t)MROWS * DIMM];
__device__ __half g_kh[(size_t)MROWS * KVD];
__device__ __half g_vh[(size_t)MROWS * KVD];
__device__ __half g_ah[(size_t)MROWS * DIMM];

__device__ __forceinline__ uint32_t f2h2(float a, float b) {
    __half2 h = __float22half2_rn(make_float2(a, b));
    return *reinterpret_cast<uint32_t*>(&h);
}
__device__ __forceinline__ float ex2(float x) {
    float r;
    asm("ex2.approx.f32 %0, %1;" : "=f"(r) : "f"(x));
    return r;
}
__device__ __forceinline__ void mma16816(float* d, const uint32_t* a,
                                         uint32_t b0, uint32_t b1) {
    asm volatile(
        "mma.sync.aligned.m16n8k16.row.col.f32.f16.f16.f32 "
        "{%0,%1,%2,%3},{%4,%5,%6,%7},{%8,%9},{%0,%1,%2,%3};"
        : "+f"(d[0]), "+f"(d[1]), "+f"(d[2]), "+f"(d[3])
        : "r"(a[0]), "r"(a[1]), "r"(a[2]), "r"(a[3]), "r"(b0), "r"(b1));
}
__device__ __forceinline__ void ldsm4(uint32_t* r, uint32_t addr) {
    asm volatile("ldmatrix.sync.aligned.m8n8.x4.shared.b16 {%0,%1,%2,%3}, [%4];"
                 : "=r"(r[0]), "=r"(r[1]), "=r"(r[2]), "=r"(r[3]) : "r"(addr));
}
__device__ __forceinline__ void ldsm4t(uint32_t* r, uint32_t addr) {
    asm volatile("ldmatrix.sync.aligned.m8n8.x4.trans.shared.b16 {%0,%1,%2,%3}, [%4];"
                 : "=r"(r[0]), "=r"(r[1]), "=r"(r[2]), "=r"(r[3]) : "r"(addr));
}
__device__ __forceinline__ void cpa16(uint32_t dst, const void* src) {
    asm volatile("cp.async.cg.shared.global [%0], [%1], 16;" :: "r"(dst), "l"(src));
}
#define CP_COMMIT() asm volatile("cp.async.commit_group;")

// log2e / sqrt(hd) folded into Q at projection epilogue
#define QSCL (0.08838834764831845f * 1.44269504088896340736f)
#define ONES2 0x3C003C00u   // half2(1.0, 1.0)

// ---------------- fp32 -> fp16 convert (64B per thread) ----------------------
__global__ void f2h_kernel(const float* __restrict__ in, __half* __restrict__ out,
                           int n16) {
    int i = blockIdx.x * blockDim.x + threadIdx.x;
    if (i >= n16) return;
    const float4* p = reinterpret_cast<const float4*>(in) + 4 * (size_t)i;
    float4 a = p[0], b = p[1], c = p[2], d = p[3];
    uint4* q = reinterpret_cast<uint4*>(out) + 2 * (size_t)i;
    q[0] = make_uint4(f2h2(a.x, a.y), f2h2(a.z, a.w), f2h2(b.x, b.y), f2h2(b.z, b.w));
    q[1] = make_uint4(f2h2(c.x, c.y), f2h2(c.z, c.w), f2h2(d.x, d.y), f2h2(d.z, d.w));
}

// ============================================================================
// fp16 GEMM, 3-stage cp.async pipeline (R9-proven config):
// CTA 128x128x64(halves), 8 warps (2x4), warp tile 64x32.
// smem rows: 64 halves = 8 x 16B chunks, phys chunk = ch ^ (row & 7).
// mode 0: fp32 out; mode 1: segmented fp16 q/k/v out, fused RoPE (+QSCL on q).
// ============================================================================
#define GBM 128
#define GBN 128
#define GBK 64
#define G_STAGE_BYTES ((GBM + GBN) * GBK * 2)     // 32768
#define G_SMEM (3 * G_STAGE_BYTES)                // 98304

__global__ __launch_bounds__(256, 2) void h16_gemm(
    const __half* __restrict__ A, const __half* __restrict__ B, int K,
    float* __restrict__ Cf,
    __half* __restrict__ qo, __half* __restrict__ ko, __half* __restrict__ vo,
    const float* __restrict__ fc, const float* __restrict__ fs, int mode) {
    extern __shared__ __half smh[];
    const uint32_t smb = (uint32_t)__cvta_generic_to_shared(smh);

    const int tid = threadIdx.x, lane = tid & 31, wid = tid >> 5;
    const int bm = blockIdx.y * GBM, bn = blockIdx.x * GBN;
    const int wm = (wid & 1) * 64, wn = (wid >> 1) * 32;

    const int srow = tid >> 1;
    const int scb  = (tid & 1) * 4;
    const __half* Agp = A + (size_t)(bm + srow) * K + scb * 8;
    const __half* Bgp = B + (size_t)(bn + srow) * K + scb * 8;
    uint32_t adst[4], bdst[4];
#pragma unroll
    for (int c = 0; c < 4; c++) {
        const int sw = (scb + c) ^ (srow & 7);
        adst[c] = (uint32_t)((srow * 8 + sw) * 16);
        bdst[c] = adst[c] + (uint32_t)(GBM * GBK * 2);
    }

    float acc[4][4][4];
#pragma unroll
    for (int i = 0; i < 4; i++)
#pragma unroll
        for (int j = 0; j < 4; j++)
#pragma unroll
            for (int c = 0; c < 4; c++) acc[i][j][c] = 0.f;

    const int T = K / GBK;
#pragma unroll
    for (int s = 0; s < 2; s++) {
        const uint32_t sb = smb + s * G_STAGE_BYTES;
#pragma unroll
        for (int c = 0; c < 4; c++) {
            cpa16(sb + adst[c], Agp + (size_t)s * GBK + c * 8);
            cpa16(sb + bdst[c], Bgp + (size_t)s * GBK + c * 8);
        }
        CP_COMMIT();
    }
    asm volatile("cp.async.wait_group 1;");
    __syncthreads();

    const int grp = lane >> 3, ls = lane & 7, qa = lane >> 2;

    int rs = 0;
    for (int t = 0; t < T; t++) {
        const int wt = t + 2;
        if (wt < T) {
            const int wsx = (rs + 2) % 3;
            const uint32_t sb = smb + wsx * G_STAGE_BYTES;
#pragma unroll
            for (int c = 0; c < 4; c++) {
                cpa16(sb + adst[c], Agp + (size_t)wt * GBK + c * 8);
                cpa16(sb + bdst[c], Bgp + (size_t)wt * GBK + c * 8);
            }
        }
        CP_COMMIT();

        const uint32_t Ab = smb + rs * G_STAGE_BYTES;
        const uint32_t Bb = Ab + (uint32_t)(GBM * GBK * 2);
#pragma unroll
        for (int kk = 0; kk < 4; kk++) {
            uint32_t af[4][4], bf[2][4];
#pragma unroll
            for (int mt = 0; mt < 4; mt++) {
                const int row = wm + mt * 16 + ls + ((grp & 1) << 3);
                const int ch  = 2 * kk + (grp >> 1);
                ldsm4(af[mt], Ab + ((row * 8 + (ch ^ (row & 7))) << 4));
            }
#pragma unroll
            for (int g = 0; g < 2; g++) {
                const int row = wn + g * 16 + ls + ((grp >> 1) << 3);
                const int ch  = 2 * kk + (grp & 1);
                ldsm4(bf[g], Bb + ((row * 8 + (ch ^ (row & 7))) << 4));
            }
#pragma unroll
            for (int mt = 0; mt < 4; mt++)
#pragma unroll
                for (int g = 0; g < 2; g++) {
                    mma16816(acc[mt][2 * g],     af[mt], bf[g][0], bf[g][1]);
                    mma16816(acc[mt][2 * g + 1], af[mt], bf[g][2], bf[g][3]);
                }
        }

        asm volatile("cp.async.wait_group 1;");
        __syncthreads();
        rs = (rs + 1) % 3;
    }

    // ---------------- epilogue ----------------
    if (mode == 0) {
#pragma unroll
        for (int mt = 0; mt < 4; mt++)
#pragma unroll
            for (int nt = 0; nt < 4; nt++) {
                const int row = bm + wm + mt * 16 + qa;
                const int col = bn + wn + nt * 8 + (lane & 3) * 2;
                *reinterpret_cast<float2*>(&Cf[(size_t)row * DIMM + col]) =
                    make_float2(acc[mt][nt][0], acc[mt][nt][1]);
                *reinterpret_cast<float2*>(&Cf[(size_t)(row + 8) * DIMM + col]) =
                    make_float2(acc[mt][nt][2], acc[mt][nt][3]);
            }
    } else {
        __half* outp; int colbase, stride; bool rope; float oscl;
        if (bn < DIMM)            { outp = qo; colbase = bn;              stride = DIMM; rope = true;  oscl = QSCL; }
        else if (bn < DIMM + KVD) { outp = ko; colbase = bn - DIMM;       stride = KVD;  rope = true;  oscl = 1.f; }
        else                      { outp = vo; colbase = bn - DIMM - KVD; stride = KVD;  rope = false; oscl = 1.f; }
#pragma unroll
        for (int mt = 0; mt < 4; mt++)
#pragma unroll
            for (int nt = 0; nt < 4; nt++) {
                const int row0 = bm + wm + mt * 16 + qa;
                const int row1 = row0 + 8;
                const int col  = colbase + wn + nt * 8 + (lane & 3) * 2;
                float2 v0 = make_float2(acc[mt][nt][0], acc[mt][nt][1]);
                float2 v1 = make_float2(acc[mt][nt][2], acc[mt][nt][3]);
                if (rope) {
                    const int i = (col & (HD - 1)) >> 1;
                    const float c0 = fc[(row0 & (SEQ - 1)) * (HD / 2) + i] * oscl;
                    const float s0 = fs[(row0 & (SEQ - 1)) * (HD / 2) + i] * oscl;
                    v0 = make_float2(v0.x * c0 - v0.y * s0, v0.x * s0 + v0.y * c0);
                    const float c1 = fc[(row1 & (SEQ - 1)) * (HD / 2) + i] * oscl;
                    const float s1 = fs[(row1 & (SEQ - 1)) * (HD / 2) + i] * oscl;
                    v1 = make_float2(v1.x * c1 - v1.y * s1, v1.x * s1 + v1.y * c1);
                }
                *reinterpret_cast<uint32_t*>(&outp[(size_t)row0 * stride + col]) = f2h2(v0.x, v0.y);
                *reinterpret_cast<uint32_t*>(&outp[(size_t)row1 * stride + col]) = f2h2(v1.x, v1.y);
            }
    }
}

// ============================================================================
// fp16 flash attention (GQA 4:1), cp.async double-buffered K/V
// Q pre-scaled by 1/sqrt(hd)*log2e; MUFU ex2.approx softmax; tensor-core lsum.
// Q-tile PAIRING: each CTA processes tiles (pair, 15-pair) -> uniform 34
// KV-tile units per CTA, 512 CTAs, ~1.7 balanced waves.
// ============================================================================
#define FBR 128
#define FBC 64
#define NQT (SEQ / FBR)      // 16
#define FQB 0u
#define FKB 32768u
#define FVB 65536u
#define FKVSZ 16384u
#define F_SMEM 98304

__global__ __launch_bounds__(256, 2) void flash_h_kernel(const __half* __restrict__ q,
                                                         const __half* __restrict__ k,
                                                         const __half* __restrict__ v,
                                                         __half* __restrict__ o) {
    extern __shared__ __half smh[];
    const uint32_t smb = (uint32_t)__cvta_generic_to_shared(smh);

    const int tid  = threadIdx.x;
    const int lane = tid & 31;
    const int wid  = tid >> 5;
    const int wm   = wid * 16;

    const int pair = blockIdx.x;                 // 0..NQT/2-1
    const int h    = blockIdx.y;
    const int b    = blockIdx.z;
    const int kvh  = h >> 2;

    const int qrow_st = tid >> 1, qcb = (tid & 1) * 8;
    const int kvrow = tid >> 2, kvcb = (tid & 3) * 4;
    uint32_t kvdst[4];
#pragma unroll
    for (int c = 0; c < 4; c++)
        kvdst[c] = (uint32_t)((kvrow * 16 + ((kvcb + c) ^ (kvrow & 7))) << 4);

    const int grp = lane >> 3, ls = lane & 7;

    for (int half = 0; half < 2; half++) {
        const int qt = half == 0 ? pair : (NQT - 1 - pair);
        const int qbase = qt * FBR;
        const int nkt = 2 * qt + 2;

        // load Q tile + first KV tile
        {
            const __half* src =
                &q[(((size_t)b * SEQ + qbase + qrow_st) * NH + h) * HD + qcb * 8];
#pragma unroll
            for (int c = 0; c < 8; c++) {
                const int ch = qcb + c;
                cpa16(smb + FQB + ((qrow_st * 16 + (ch ^ (qrow_st & 7))) << 4),
                      src + c * 8);
            }
            const size_t base = (((size_t)b * SEQ + kvrow) * NKV + kvh) * HD + kvcb * 8;
#pragma unroll
            for (int c = 0; c < 4; c++) {
                cpa16(smb + FKB + kvdst[c], &k[base + c * 8]);
                cpa16(smb + FVB + kvdst[c], &v[base + c * 8]);
            }
        }
        CP_COMMIT();
        asm volatile("cp.async.wait_group 0;");
        __syncthreads();

        float oacc[16][4];
#pragma unroll
        for (int n = 0; n < 16; n++)
#pragma unroll
            for (int c = 0; c < 4; c++) oacc[n][c] = 0.f;
        float m0 = -INFINITY, m1 = -INFINITY, l0 = 0.f, l1 = 0.f;

        for (int kt = 0; kt < nkt; kt++) {
            const int kvbase = kt * FBC;
            if (kt + 1 < nkt) {
                const uint32_t ob = ((kt + 1) & 1) * FKVSZ;
                const size_t base =
                    (((size_t)b * SEQ + (kt + 1) * FBC + kvrow) * NKV + kvh) * HD + kvcb * 8;
#pragma unroll
                for (int c = 0; c < 4; c++) {
                    cpa16(smb + FKB + ob + kvdst[c], &k[base + c * 8]);
                    cpa16(smb + FVB + ob + kvdst[c], &v[base + c * 8]);
                }
            }
            CP_COMMIT();

            const uint32_t ksb = smb + FKB + (kt & 1) * FKVSZ;
            const uint32_t vsb = smb + FVB + (kt & 1) * FKVSZ;
            const uint32_t qsb = smb + FQB;

            float sacc[8][4];
#pragma unroll
            for (int n = 0; n < 8; n++)
#pragma unroll
                for (int c = 0; c < 4; c++) sacc[n][c] = 0.f;

#pragma unroll
            for (int i = 0; i < HD / 16; i++) {
                uint32_t qf[4], kf[4];
                const int qrow = wm + ls + ((grp & 1) << 3);
                const int qch  = 2 * i + (grp >> 1);
                ldsm4(qf, qsb + (((qrow << 4) + (qch ^ (qrow & 7))) << 4));
#pragma unroll
                for (int n0 = 0; n0 < 4; n0++) {
                    const int krow = n0 * 16 + ls + ((grp >> 1) << 3);
                    const int kch  = 2 * i + (grp & 1);
                    ldsm4(kf, ksb + (((krow << 4) + (kch ^ (krow & 7))) << 4));
                    mma16816(sacc[2 * n0],     qf, kf[0], kf[1]);
                    mma16816(sacc[2 * n0 + 1], qf, kf[2], kf[3]);
                }
            }

            const int gr0 = qbase + wm + (lane >> 2);
            const int gr1 = gr0 + 8;
            const bool need_mask = (kvbase + FBC - 1) > (qbase + wm);
            if (need_mask) {
#pragma unroll
                for (int n = 0; n < 8; n++) {
                    const int gc = kvbase + n * 8 + (lane & 3) * 2;
                    if (gc     > gr0) sacc[n][0] = -INFINITY;
                    if (gc + 1 > gr0) sacc[n][1] = -INFINITY;
                    if (gc     > gr1) sacc[n][2] = -INFINITY;
                    if (gc + 1 > gr1) sacc[n][3] = -INFINITY;
                }
            }

            float mx0 = -INFINITY, mx1 = -INFINITY;
#pragma unroll
            for (int n = 0; n < 8; n++) {
                mx0 = fmaxf(mx0, fmaxf(sacc[n][0], sacc[n][1]));
                mx1 = fmaxf(mx1, fmaxf(sacc[n][2], sacc[n][3]));
            }
            mx0 = fmaxf(mx0, __shfl_xor_sync(0xffffffffu, mx0, 1));
            mx0 = fmaxf(mx0, __shfl_xor_sync(0xffffffffu, mx0, 2));
            mx1 = fmaxf(mx1, __shfl_xor_sync(0xffffffffu, mx1, 1));
            mx1 = fmaxf(mx1, __shfl_xor_sync(0xffffffffu, mx1, 2));

            const float mn0 = fmaxf(m0, mx0);
            const float mn1 = fmaxf(m1, mx1);
            const float al0 = ex2(m0 - mn0);
            const float al1 = ex2(m1 - mn1);
            m0 = mn0; m1 = mn1;

            uint32_t ph[8][2];
#pragma unroll
            for (int n = 0; n < 8; n++) {
                const float p0 = ex2(sacc[n][0] - m0);
                const float p1 = ex2(sacc[n][1] - m0);
                const float p2 = ex2(sacc[n][2] - m1);
                const float p3 = ex2(sacc[n][3] - m1);
                ph[n][0] = f2h2(p0, p1);
                ph[n][1] = f2h2(p2, p3);
            }

            float lsum[4] = {0.f, 0.f, 0.f, 0.f};
#pragma unroll
            for (int j = 0; j < FBC / 16; j++) {
                uint32_t pa[4] = {ph[2*j][0], ph[2*j][1], ph[2*j+1][0], ph[2*j+1][1]};
                mma16816(lsum, pa, ONES2, ONES2);
            }
            l0 = l0 * al0 + lsum[0];
            l1 = l1 * al1 + lsum[2];

#pragma unroll
            for (int n = 0; n < 16; n++) {
                oacc[n][0] *= al0; oacc[n][1] *= al0;
                oacc[n][2] *= al1; oacc[n][3] *= al1;
            }

#pragma unroll
            for (int j = 0; j < FBC / 16; j++) {
                uint32_t pa[4] = {ph[2*j][0], ph[2*j][1], ph[2*j+1][0], ph[2*j+1][1]};
#pragma unroll
                for (int n0 = 0; n0 < HD / 16; n0++) {
                    uint32_t vf[4];
                    const int vrow = j * 16 + ls + ((grp & 1) << 3);
                    const int vch  = 2 * n0 + (grp >> 1);
                    ldsm4t(vf, vsb + (((vrow << 4) + (vch ^ (vrow & 7))) << 4));
                    mma16816(oacc[2 * n0],     pa, vf[0], vf[1]);
                    mma16816(oacc[2 * n0 + 1], pa, vf[2], vf[3]);
                }
            }

            asm volatile("cp.async.wait_group 0;");
            __syncthreads();
        }

        // epilogue for this half
        const float inv0 = 1.f / l0;
        const float inv1 = 1.f / l1;
        const int gr0 = qbase + wm + (lane >> 2);
        const int gr1 = gr0 + 8;
#pragma unroll
        for (int n = 0; n < 16; n++) {
            const int col = n * 8 + (lane & 3) * 2;
            *reinterpret_cast<uint32_t*>(
                &o[((size_t)b * SEQ + gr0) * DIMM + h * HD + col]) =
                f2h2(oacc[n][0] * inv0, oacc[n][1] * inv0);
            *reinterpret_cast<uint32_t*>(
                &o[((size_t)b * SEQ + gr1) * DIMM + h * HD + col]) =
                f2h2(oacc[n][2] * inv1, oacc[n][3] * inv1);
        }
    }
}

// ---------------- launch ------------------------------------------------------
extern "C" void kernel_launch(void* const* d_in, const int* in_sizes, int n_in,
                              void* d_out, int out_size) {
    const float* x  = (const float*)d_in[0];
    const float* wq = (const float*)d_in[1];
    const float* wk = (const float*)d_in[2];
    const float* wv = (const float*)d_in[3];
    const float* wo = (const float*)d_in[4];
    const float* fc = (const float*)d_in[5];
    const float* fs = (const float*)d_in[6];
    float* out = (float*)d_out;

    __half *xh, *wh, *woh, *qh, *kh, *vh, *ah;
    cudaGetSymbolAddress((void**)&xh,  g_xh);
    cudaGetSymbolAddress((void**)&wh,  g_wh);
    cudaGetSymbolAddress((void**)&woh, g_woh);
    cudaGetSymbolAddress((void**)&qh,  g_qh);
    cudaGetSymbolAddress((void**)&kh,  g_kh);
    cudaGetSymbolAddress((void**)&vh,  g_vh);
    cudaGetSymbolAddress((void**)&ah,  g_ah);

    cudaFuncSetAttribute(h16_gemm, cudaFuncAttributeMaxDynamicSharedMemorySize, G_SMEM);
    cudaFuncSetAttribute(flash_h_kernel, cudaFuncAttributeMaxDynamicSharedMemorySize, F_SMEM);

    // fp32 -> fp16 converts (five separate launches — proven)
    {
        const int nx = MROWS * DIMM / 16;
        f2h_kernel<<<nx / 256, 256>>>(x, xh, nx);
        const int nq = DIMM * DIMM / 16;
        f2h_kernel<<<nq / 256, 256>>>(wq, wh, nq);
        const int nk = KVD * DIMM / 16;
        f2h_kernel<<<nk / 256, 256>>>(wk, wh + (size_t)DIMM * DIMM, nk);
        f2h_kernel<<<nk / 256, 256>>>(wv, wh + (size_t)(DIMM + KVD) * DIMM, nk);
        f2h_kernel<<<nq / 256, 256>>>(wo, woh, nq);
    }

    // fused QKV projection + RoPE (+QSCL on q)
    h16_gemm<<<dim3(NQKV / GBN, MROWS / GBM), 256, G_SMEM>>>(
        xh, wh, DIMM, nullptr, qh, kh, vh, fc, fs, 1);

    // causal flash attention (paired Q tiles, balanced CTAs)
    flash_h_kernel<<<dim3(NQT / 2, NH, BATCH), 256, F_SMEM>>>(qh, kh, vh, ah);

    // output projection (fp32 out)
    h16_gemm<<<dim3(DIMM / GBN, MROWS / GBM), 256, G_SMEM>>>(
        ah, woh, DIMM, out, nullptr, nullptr, nullptr, nullptr, nullptr, 0);
}